// round 14
// baseline (speedup 1.0000x reference)
#include <cuda_runtime.h>
#include <math.h>

// ---------------------------------------------------------------------------
// HierarchicalCNN: two 3-layer strided conv1d nets + pooled heads + routing.
// Both conv stages on tf32 mma.sync m16n8k8 (single pass, rna).
//
// R14: occupancy push. CTA tile 128co x 64t (warp tile 32x32, acc = 32
// regs), __launch_bounds__(256,3) -> 3 CTAs/SM (24 warps, was 16).
// Packed pitch-16 smem with seg-XOR swizzle (validated R13):
//   float offset f in row -> ((f>>2) ^ (row&3))<<2 | (f&3)
// Column interleave pos(ci) = (ci>>3)*8 + (ci&3)*2 + ((ci>>2)&1) makes each
// fragment operand one LDS.64, conflict-free.
// tap -> (parity, row offset): k0:(odd,0) k1:(even,0) k2:(odd,1)
//                              k3:(even,1) k4:(odd,2)
// Simple phase structure (stage -> sync -> mma -> sync); A via cp.async.
// conv01 staging computes conv0 on the fly with fma.rn.f32x2 (pre-paired
// weights, pairs (ci,ci+4) adjacent in the interleave).
// ---------------------------------------------------------------------------

typedef unsigned int       u32;
typedef unsigned long long ull;

__device__ float g_a1[(size_t)512 * 128 * 1024];
__device__ float g_feat[2][512][256];
// tf32 conv1 weights, interleaved cols: [net][chunk 4][tap 5][co 128][pos 16]
__device__ __align__(16) float g_w1tf[2][4][5][128][16];
// tf32 conv2 weights: [net][coh 2][chunk 8][tap 5][co 128][pos 16]
__device__ __align__(16) float g_w2tf[2][2][8][5][128][16];

// ---------------- helpers ---------------------------------------------------
__device__ __forceinline__ u32 to_tf32(float v) {
    u32 r;
    asm("cvt.rna.tf32.f32 %0, %1;" : "=r"(r) : "f"(v));
    return r;
}
__device__ __forceinline__ void mma_tf32(float* d, const u32* a, u32 b0, u32 b1) {
    asm volatile(
        "mma.sync.aligned.m16n8k8.row.col.f32.tf32.tf32.f32 "
        "{%0,%1,%2,%3}, {%4,%5,%6,%7}, {%8,%9}, {%0,%1,%2,%3};"
        : "+f"(d[0]), "+f"(d[1]), "+f"(d[2]), "+f"(d[3])
        : "r"(a[0]), "r"(a[1]), "r"(a[2]), "r"(a[3]), "r"(b0), "r"(b1));
}
__device__ __forceinline__ void fma2(ull& d, ull a, ull b) {
    asm("fma.rn.f32x2 %0, %1, %2, %0;" : "+l"(d) : "l"(a), "l"(b));
}
__device__ __forceinline__ ull pack2(float lo, float hi) {
    ull r;
    asm("mov.b64 %0, {%1, %2};" : "=l"(r) : "f"(lo), "f"(hi));
    return r;
}
__device__ __forceinline__ void unpack2(ull v, float& lo, float& hi) {
    asm("mov.b64 {%0, %1}, %2;" : "=f"(lo), "=f"(hi) : "l"(v));
}
__device__ __forceinline__ u32 smem_u32(const void* p) {
    u32 a;
    asm("{ .reg .u64 t; cvta.to.shared.u64 t, %1; cvt.u32.u64 %0, t; }"
        : "=r"(a) : "l"(p));
    return a;
}
__device__ __forceinline__ void cp16(u32 dst, const void* src) {
    asm volatile("cp.async.cg.shared.global [%0], [%1], 16;" :: "r"(dst), "l"(src));
}
#define CP_COMMIT() asm volatile("cp.async.commit_group;" ::: "memory")
#define CP_WAIT0()  asm volatile("cp.async.wait_group 0;" ::: "memory")

__host__ __device__ constexpr int posi(int ci) {
    return ((ci >> 3) << 3) + ((ci & 3) << 1) + ((ci >> 2) & 1);
}
__device__ __forceinline__ int swzf(int f, int s) {
    return ((((f >> 2) ^ s) << 2) | (f & 3));
}

#define A_FLTS (5 * 128 * 16)   // 10240
#define B_ROWS 68
#define B_FLTS (B_ROWS * 16)    // 1088

// ---------------------------------------------------------------------------
// prep kernels (packed [co][pos 16] tiles; swizzle applied at staging time)
// ---------------------------------------------------------------------------
__global__ __launch_bounds__(256)
void prep_w1_kernel(const float* __restrict__ w_n0, const float* __restrict__ w_n1)
{
    int idx = blockIdx.x * 256 + threadIdx.x;
    const int total = 2 * 4 * 5 * 128 * 16;
    if (idx >= total) return;
    int r = idx;
    int ci = r & 15;   r >>= 4;
    int co = r & 127;  r >>= 7;
    int tap = r % 5;   r /= 5;
    int chunk = r & 3; r >>= 2;
    int net = r;
    const float* w = net ? w_n1 : w_n0;
    float v = w[(size_t)co * 320 + (chunk * 16 + ci) * 5 + tap];
    g_w1tf[net][chunk][tap][co][posi(ci)] = __uint_as_float(to_tf32(v));
}

__global__ __launch_bounds__(256)
void prep_w2_kernel(const float* __restrict__ w_n0, const float* __restrict__ w_n1)
{
    int idx = blockIdx.x * 256 + threadIdx.x;
    const int total = 2 * 2 * 8 * 5 * 128 * 16;
    if (idx >= total) return;
    int r = idx;
    int ci = r & 15;   r >>= 4;
    int co = r & 127;  r >>= 7;
    int tap = r % 5;   r /= 5;
    int chunk = r & 7; r >>= 3;
    int coh = r & 1;   r >>= 1;
    int net = r;
    const float* w = net ? w_n1 : w_n0;
    float v = w[(size_t)(coh * 128 + co) * 640 + (chunk * 16 + ci) * 5 + tap];
    g_w2tf[net][coh][chunk][tap][co][posi(ci)] = __uint_as_float(to_tf32(v));
}

// ---------------------------------------------------------------------------
// A stage: cp.async packed [640 rows][16] -> swizzled pitch-16 smem tile
// ---------------------------------------------------------------------------
#define STAGE_A(uAs, srcp)                                                     \
    {                                                                          \
        const char* _src = (const char*)(srcp);                                \
        _Pragma("unroll")                                                      \
        for (int r = 0; r < 10; r++) {                                         \
            int i = r * 256 + tid;                                             \
            int row = i >> 2, seg = i & 3;                                     \
            int off = (row << 4) + (((seg ^ (row & 3)) << 2));                 \
            cp16((uAs) + (u32)off * 4, _src + (size_t)i * 16);                 \
        }                                                                      \
        CP_COMMIT();                                                           \
    }

// ---------------------------------------------------------------------------
// MMA over one staged chunk (5 taps), warp tile 32co x 32t (j = 0..3).
// ---------------------------------------------------------------------------
#define MMA_CHUNK(As, BeT, BoT)                                                \
    {                                                                          \
        const int sA = lr & 3;                                                 \
        const int offA0 = swzf(2 * lc, sA);                                    \
        const int offA1 = swzf(2 * lc + 8, sA);                                \
        _Pragma("unroll")                                                      \
        for (int tap = 0; tap < 5; tap++) {                                    \
            const float* Bb = (tap == 1 || tap == 3) ? (BeT) : (BoT);          \
            const int roff = (tap < 2) ? 0 : ((tap == 4) ? 2 : 1);             \
            const int sB = (lr + roff) & 3;                                    \
            const int offB0 = swzf(2 * lc, sB);                                \
            const int offB1 = swzf(2 * lc + 8, sB);                            \
            u32 a[2][2][4];                                                    \
            _Pragma("unroll")                                                  \
            for (int m = 0; m < 2; m++) {                                      \
                const float* ab = (As) + (tap * 128 + wco + m * 16 + lr) * 16; \
                _Pragma("unroll")                                              \
                for (int h = 0; h < 2; h++) {                                  \
                    int oa = h ? offA1 : offA0;                                \
                    float2 q0 = *(const float2*)&ab[oa];                       \
                    float2 q1 = *(const float2*)&ab[128 + oa];                 \
                    a[m][h][0] = __float_as_uint(q0.x);                        \
                    a[m][h][1] = __float_as_uint(q1.x);                        \
                    a[m][h][2] = __float_as_uint(q0.y);                        \
                    a[m][h][3] = __float_as_uint(q1.y);                        \
                }                                                              \
            }                                                                  \
            const float* bb = Bb + (wt + lr + roff) * 16;                      \
            _Pragma("unroll")                                                  \
            for (int h = 0; h < 2; h++) {                                      \
                int ob = h ? offB1 : offB0;                                    \
                _Pragma("unroll")                                              \
                for (int j = 0; j < 4; j++) {                                  \
                    float2 p = *(const float2*)&bb[j * 128 + ob];              \
                    u32 pb0 = __float_as_uint(p.x);                            \
                    u32 pb1 = __float_as_uint(p.y);                            \
                    mma_tf32(acc[0][j], a[0][h], pb0, pb1);                    \
                    mma_tf32(acc[1][j], a[1][h], pb0, pb1);                    \
                }                                                              \
            }                                                                  \
        }                                                                      \
    }

// ---------------------------------------------------------------------------
// conv01: conv0 on the fly (fma2) + conv1 tf32 mma.
// grid (512 b, 16 t-tiles), 256 threads. CTA 128co x 64t.
// smem floats: As[10240] | Be[1088] | Bo[1088] | xs0[532] | w0d[640] | b0d[64]
// ---------------------------------------------------------------------------
#define O1_BE  A_FLTS
#define O1_BO  (O1_BE + B_FLTS)
#define O1_X   (O1_BO + B_FLTS)      // xs0: 2 x 266
#define O1_W   (O1_X + 532)
#define O1_BD  (O1_W + 640)
#define C1_SMEM ((O1_BD + 64) * 4)   // 54,616 bytes -> 3 CTAs/SM

__global__ __launch_bounds__(256, 3)
void conv01_mma_kernel(const float* __restrict__ x,
                       const float* __restrict__ w0,  // [64,2,5]
                       const float* __restrict__ b0,  // [64]
                       const float* __restrict__ b1,  // [128]
                       float* __restrict__ out,       // [512,128,1024]
                       int net)
{
    extern __shared__ float sm[];
    float* As  = sm;
    float* Be  = sm + O1_BE;
    float* Bo  = sm + O1_BO;
    float* xs0 = sm + O1_X;
    ull*   w0d = (ull*)(sm + O1_W);   // [chunk4][grp8][k10] pairs (ci, ci+4)
    ull*   b0d = (ull*)(sm + O1_BD);  // [chunk4][grp8]

    const int tid  = threadIdx.x;
    const int lane = tid & 31;
    const int wid  = tid >> 5;
    const int b    = blockIdx.x;
    const int tt0  = blockIdx.y * 64;

    const int wco = (wid & 3) * 32;
    const int wt  = (wid >> 2) * 32;
    const int lr  = lane >> 2;
    const int lc  = lane & 3;
    const u32 uAs = smem_u32(As);

    // ---- one-time loads: x window (266 wide), paired w0/b0 ----
    {
        const int x0 = 4 * tt0 - 3;
        const float* xb = x + (size_t)b * 2 * 4096;
#pragma unroll
        for (int row = 0; row < 2; row++)
            for (int col = tid; col < 266; col += 256) {
                int gx = x0 + col;
                xs0[row * 266 + col] =
                    (gx >= 0 && gx < 4096) ? xb[(size_t)row * 4096 + gx] : 0.0f;
            }
        for (int i = tid; i < 320; i += 256) {
            int k = i % 10, g = (i / 10) & 7, ch = i / 80;
            int ci = ch * 16 + (g & 3) + ((g >> 2) << 3);
            w0d[i] = pack2(w0[ci * 10 + k], w0[(ci + 4) * 10 + k]);
        }
        if (tid < 32) {
            int ch = tid >> 3, g = tid & 7;
            int ci = ch * 16 + (g & 3) + ((g >> 2) << 3);
            b0d[tid] = pack2(b0[ci], b0[ci + 4]);
        }
    }

    float acc[2][4][4];
#pragma unroll
    for (int m = 0; m < 2; m++)
#pragma unroll
        for (int j = 0; j < 4; j++)
#pragma unroll
            for (int e = 0; e < 4; e++) acc[m][j][e] = 0.0f;

    __syncthreads();   // xs0/w0d visible

    for (int chunk = 0; chunk < 4; chunk++) {
        // ---- A stage (cp.async, overlaps B compute below) ----
        STAGE_A(uAs, &g_w1tf[net][chunk][0][0][0]);

        // ---- B stage: conv0 via fma2 into swizzled parity-split tiles ----
        // rows: Be 0..64 (65), Bo 0..65 (66) -> 131 rows, one per thread
        {
            const ull* wch = w0d + chunk * 80;
            const ull* bch = b0d + chunk * 8;
            int r = tid;
            if (r < 131) {
                int tau, cb, sB;
                float* dst;
                if (r < 65) {            // even: Be[r] = a0(2*tt0 + 2r)
                    tau = 2 * tt0 + 2 * r;
                    cb  = 4 * r + 2;
                    dst = Be + r * 16;
                    sB  = r & 3;
                } else {                 // odd: Bo[mm] = a0(2*tt0 + 2mm - 1)
                    int mm = r - 65;
                    tau = 2 * tt0 + 2 * mm - 1;
                    cb  = 4 * mm;
                    dst = Bo + mm * 16;
                    sB  = mm & 3;
                }
                if (tau >= 0 && tau < 2048) {
                    ull xp[10];
#pragma unroll
                    for (int k = 0; k < 5; k++) {
                        float v = xs0[cb + k];
                        xp[k] = pack2(v, v);
                    }
#pragma unroll
                    for (int k = 0; k < 5; k++) {
                        float v = xs0[266 + cb + k];
                        xp[5 + k] = pack2(v, v);
                    }
#pragma unroll
                    for (int g = 0; g < 8; g++) {
                        ull a2 = bch[g];
                        const ull* wg = wch + g * 10;
#pragma unroll
                        for (int q = 0; q < 10; q++) fma2(a2, wg[q], xp[q]);
                        float lo, hi;
                        unpack2(a2, lo, hi);
                        float2 vv = make_float2(
                            __uint_as_float(to_tf32(fmaxf(lo, 0.0f))),
                            __uint_as_float(to_tf32(fmaxf(hi, 0.0f))));
                        int off = (((g >> 1) ^ sB) << 2) | ((g & 1) << 1);
                        *(float2*)&dst[off] = vv;
                    }
                } else {
#pragma unroll
                    for (int g = 0; g < 8; g++) {
                        int off = (((g >> 1) ^ sB) << 2) | ((g & 1) << 1);
                        *(float2*)&dst[off] = make_float2(0.0f, 0.0f);
                    }
                }
            }
        }
        CP_WAIT0();
        __syncthreads();

        MMA_CHUNK(As, Be, Bo)
        __syncthreads();
    }

    // ---- epilogue: bias+relu, write a1; t = wt + j*8 + 2lc (+1) ----
#pragma unroll
    for (int m = 0; m < 2; m++) {
        int co_a = wco + m * 16 + lr;
        int co_b = co_a + 8;
        float bva = b1[co_a];
        float bvb = b1[co_b];
        float* oa = out + ((size_t)b * 128 + co_a) * 1024 + tt0;
        float* ob = out + ((size_t)b * 128 + co_b) * 1024 + tt0;
#pragma unroll
        for (int j = 0; j < 4; j++) {
            int t = wt + j * 8 + 2 * lc;
            *(float2*)&oa[t] = make_float2(fmaxf(acc[m][j][0] + bva, 0.0f),
                                           fmaxf(acc[m][j][1] + bva, 0.0f));
            *(float2*)&ob[t] = make_float2(fmaxf(acc[m][j][2] + bvb, 0.0f),
                                           fmaxf(acc[m][j][3] + bvb, 0.0f));
        }
    }
}

// ---------------------------------------------------------------------------
// conv2: tf32 warp-MMA + fused pool. grid (512, 8, 2), 256 thr. CTA 128x64.
// smem floats: As[10240] | Be[1088] | Bo[1088]
// ---------------------------------------------------------------------------
#define O2_BE  A_FLTS
#define O2_BO  (O2_BE + B_FLTS)
#define C2_SMEM ((O2_BO + B_FLTS) * 4)   // 49,664 bytes -> 3 CTAs/SM

__global__ __launch_bounds__(256, 3)
void conv2_mma_kernel(const float* __restrict__ in,    // [512,128,1024] fp32
                      const float* __restrict__ bias,  // [256]
                      float* __restrict__ feat,        // [512,256] sums
                      int net)
{
    extern __shared__ float sm[];
    float* As = sm;
    float* Be = sm + O2_BE;
    float* Bo = sm + O2_BO;

    const int tid  = threadIdx.x;
    const int lane = tid & 31;
    const int wid  = tid >> 5;
    const int b    = blockIdx.x;
    const int tt0  = blockIdx.y * 64;
    const int co0  = blockIdx.z * 128;

    const int wco = (wid & 3) * 32;
    const int wt  = (wid >> 2) * 32;
    const int lr  = lane >> 2;
    const int lc  = lane & 3;
    const u32 uAs = smem_u32(As);

    float acc[2][4][4];
#pragma unroll
    for (int m = 0; m < 2; m++)
#pragma unroll
        for (int j = 0; j < 4; j++)
#pragma unroll
            for (int e = 0; e < 4; e++) acc[m][j][e] = 0.0f;

    const float* inb = in + (size_t)b * 128 * 1024;
    const int bci  = tid >> 4;
    const int brl  = tid & 15;
    const int pcol = posi(bci);

    for (int chunk = 0; chunk < 8; chunk++) {
        const int ci0 = chunk * 16;
        STAGE_A(uAs, &g_w2tf[net][co0 >> 7][chunk][0][0][0]);
        // ---- B stage: parity-split copy + tf32 ----
        {
            const float* arow = inb + (size_t)(ci0 + bci) * 1024;
            for (int m = brl; m < 65; m += 16) {
                int g0 = 2 * tt0 + 2 * m;
                float ev = 0.0f, od = 0.0f;
                if (g0 < 1024) {
                    float2 v = *(const float2*)&arow[g0];
                    ev = v.x; od = v.y;
                }
                Be[m * 16 + swzf(pcol, m & 3)] =
                    __uint_as_float(to_tf32(ev));
                Bo[(m + 1) * 16 + swzf(pcol, (m + 1) & 3)] =
                    __uint_as_float(to_tf32(od));
            }
            if (tid < 16) {  // odd row 0: g = 2*tt0 - 1
                float v = (tt0 > 0) ? inb[(size_t)(ci0 + tid) * 1024 + 2 * tt0 - 1]
                                    : 0.0f;
                Bo[swzf(posi(tid), 0)] = __uint_as_float(to_tf32(v));
            }
        }
        CP_WAIT0();
        __syncthreads();

        MMA_CHUNK(As, Be, Bo)
        __syncthreads();
    }

    // ---- epilogue: bias+relu, sum over t, quad-reduce, atomicAdd ----
    float* fb = feat + (size_t)b * 256;
#pragma unroll
    for (int m = 0; m < 2; m++) {
        int r0 = co0 + wco + m * 16 + lr;
        int r1 = r0 + 8;
        float bv0 = __ldg(&bias[r0]);
        float bv1 = __ldg(&bias[r1]);
        float s0 = 0.0f, s1 = 0.0f;
#pragma unroll
        for (int j = 0; j < 4; j++) {
            s0 += fmaxf(acc[m][j][0] + bv0, 0.0f) + fmaxf(acc[m][j][1] + bv0, 0.0f);
            s1 += fmaxf(acc[m][j][2] + bv1, 0.0f) + fmaxf(acc[m][j][3] + bv1, 0.0f);
        }
        s0 += __shfl_xor_sync(0xffffffffu, s0, 1);
        s0 += __shfl_xor_sync(0xffffffffu, s0, 2);
        s1 += __shfl_xor_sync(0xffffffffu, s1, 1);
        s1 += __shfl_xor_sync(0xffffffffu, s1, 2);
        if (lc == 0) {
            atomicAdd(&fb[r0], s0);
            atomicAdd(&fb[r1], s1);
        }
    }
}

// ---------------------------------------------------------------------------
__global__ void zero_feat_kernel()
{
    int i = blockIdx.x * 256 + threadIdx.x;
    if (i < 2 * 512 * 256) ((float*)g_feat)[i] = 0.0f;
}

// ---------------------------------------------------------------------------
// heads + softmax + hierarchical routing. 1 warp per sample.
// ---------------------------------------------------------------------------
__global__ __launch_bounds__(32)
void head_kernel(const float* __restrict__ wh1, const float* __restrict__ bh1,
                 const float* __restrict__ wh2, const float* __restrict__ bh2,
                 float* __restrict__ out)
{
    const int b = blockIdx.x;
    const int lane = threadIdx.x;
    const float* f1 = &g_feat[0][b][0];
    const float* f2 = &g_feat[1][b][0];
    const float inv_pool = 1.0f / 512.0f;

    float lg1[3], lg2[2];
#pragma unroll
    for (int cls = 0; cls < 3; cls++) {
        float s = 0.0f;
        for (int c = lane; c < 256; c += 32) s += f1[c] * wh1[cls * 256 + c];
#pragma unroll
        for (int off = 16; off > 0; off >>= 1) s += __shfl_xor_sync(0xffffffffu, s, off);
        lg1[cls] = s * inv_pool + bh1[cls];
    }
#pragma unroll
    for (int cls = 0; cls < 2; cls++) {
        float s = 0.0f;
        for (int c = lane; c < 256; c += 32) s += f2[c] * wh2[cls * 256 + c];
#pragma unroll
        for (int off = 16; off > 0; off >>= 1) s += __shfl_xor_sync(0xffffffffu, s, off);
        lg2[cls] = s * inv_pool + bh2[cls];
    }

    if (lane == 0) {
        float m = fmaxf(lg1[0], fmaxf(lg1[1], lg1[2]));
        float e0 = expf(lg1[0] - m), e1 = expf(lg1[1] - m), e2 = expf(lg1[2] - m);
        float inv = 1.0f / (e0 + e1 + e2);
        float p0 = e0 * inv, p1 = e1 * inv, p2 = e2 * inv;
        int pred = 0; float best = p0;
        if (p1 > best) { best = p1; pred = 1; }
        if (p2 > best) { best = p2; pred = 2; }

        float m2 = fmaxf(lg2[0], lg2[1]);
        float q0 = expf(lg2[0] - m2), q1 = expf(lg2[1] - m2);
        float inv2 = 1.0f / (q0 + q1);
        q0 *= inv2; q1 *= inv2;

        out[b * 4 + 0] = (pred == 0) ? p0 : 0.0f;
        out[b * 4 + 1] = (pred == 1) ? p1 : 0.0f;
        out[b * 4 + 2] = (pred == 2) ? q0 : 0.0f;
        out[b * 4 + 3] = (pred == 2) ? q1 : 0.0f;
    }
}

// ---------------------------------------------------------------------------
extern "C" void kernel_launch(void* const* d_in, const int* in_sizes, int n_in,
                              void* d_out, int out_size)
{
    (void)in_sizes; (void)n_in; (void)out_size;
    const float* x = (const float*)d_in[0];

    const float* W[2][8];
    for (int net = 0; net < 2; net++)
        for (int i = 0; i < 8; i++)
            W[net][i] = (const float*)d_in[1 + net * 8 + i];

    float* out = (float*)d_out;

    float *a1, *feat;
    cudaGetSymbolAddress((void**)&a1, g_a1);
    cudaGetSymbolAddress((void**)&feat, g_feat);

    cudaFuncSetAttribute(conv01_mma_kernel,
                         cudaFuncAttributeMaxDynamicSharedMemorySize, C1_SMEM);
    cudaFuncSetAttribute(conv2_mma_kernel,
                         cudaFuncAttributeMaxDynamicSharedMemorySize, C2_SMEM);

    zero_feat_kernel<<<1024, 256>>>();
    prep_w1_kernel<<<320, 256>>>(W[0][2], W[1][2]);
    prep_w2_kernel<<<1280, 256>>>(W[0][4], W[1][4]);

    for (int net = 0; net < 2; net++) {
        conv01_mma_kernel<<<dim3(512, 16), 256, C1_SMEM>>>(
            x, W[net][0], W[net][1], W[net][3], a1, net);
        conv2_mma_kernel<<<dim3(512, 8, 2), 256, C2_SMEM>>>(
            a1, W[net][5], feat + (size_t)net * 512 * 256, net);
    }

    head_kernel<<<512, 32>>>(W[0][6], W[0][7], W[1][6], W[1][7], out);
}

// round 16
// speedup vs baseline: 1.3403x; 1.3403x over previous
#include <cuda_runtime.h>
#include <math.h>

// ---------------------------------------------------------------------------
// HierarchicalCNN: two 3-layer strided conv1d nets + pooled heads + routing.
// Both conv stages on tf32 mma.sync m16n8k8 (single pass, rna).
//
// R15/R16: producer-side layout. conv01 stores its output ALREADY in conv2's
// B-tile format: parity-split (ae[r]=a1[2r], ao[r]=a1[2r-1]), tf32-rounded,
// ci-column-interleaved (posi within each 16-group). conv2's B staging is
// then pure cp.async (64B rows -> swizzled smem), no cvt, no scatter.
// Halo rows ae[512], ao[0], ao[513] are never written and stay zero from
// static initialization (conv01 never writes them; replays deterministic).
//
// Smem tiles: packed pitch-16 with seg-XOR swizzle (validated R13/R14):
//   float offset f in row -> ((f>>2) ^ (row&3))<<2 | (f&3)
// Column interleave pos(ci) = (ci>>3)*8 + (ci&3)*2 + ((ci>>2)&1).
// tap -> (parity, row offset): k0:(odd,0) k1:(even,0) k2:(odd,1)
//                              k3:(even,1) k4:(odd,2)
// Mainloops: proven R12-shape 128co x 128t CTA tiles, 2 CTAs/SM, simple
// stage -> sync -> mma -> sync phases.
// ---------------------------------------------------------------------------

typedef unsigned int       u32;
typedef unsigned long long ull;

#define AE_ROWS 514
__device__ float g_ae[512][AE_ROWS][128];   // a1[2r],   tf32, interleaved
__device__ float g_ao[512][AE_ROWS][128];   // a1[2r-1], tf32, interleaved
__device__ float g_feat[2][512][256];
// tf32 conv1 weights, interleaved cols: [net][chunk 4][tap 5][co 128][pos 16]
__device__ __align__(16) float g_w1tf[2][4][5][128][16];
// tf32 conv2 weights: [net][coh 2][chunk 8][tap 5][co 128][pos 16]
__device__ __align__(16) float g_w2tf[2][2][8][5][128][16];

// ---------------- helpers ---------------------------------------------------
__device__ __forceinline__ u32 to_tf32(float v) {
    u32 r;
    asm("cvt.rna.tf32.f32 %0, %1;" : "=r"(r) : "f"(v));
    return r;
}
__device__ __forceinline__ void mma_tf32(float* d, const u32* a, u32 b0, u32 b1) {
    asm volatile(
        "mma.sync.aligned.m16n8k8.row.col.f32.tf32.tf32.f32 "
        "{%0,%1,%2,%3}, {%4,%5,%6,%7}, {%8,%9}, {%0,%1,%2,%3};"
        : "+f"(d[0]), "+f"(d[1]), "+f"(d[2]), "+f"(d[3])
        : "r"(a[0]), "r"(a[1]), "r"(a[2]), "r"(a[3]), "r"(b0), "r"(b1));
}
__device__ __forceinline__ void fma2(ull& d, ull a, ull b) {
    asm("fma.rn.f32x2 %0, %1, %2, %0;" : "+l"(d) : "l"(a), "l"(b));
}
__device__ __forceinline__ ull pack2(float lo, float hi) {
    ull r;
    asm("mov.b64 %0, {%1, %2};" : "=l"(r) : "f"(lo), "f"(hi));
    return r;
}
__device__ __forceinline__ void unpack2(ull v, float& lo, float& hi) {
    asm("mov.b64 {%0, %1}, %2;" : "=f"(lo), "=f"(hi) : "l"(v));
}
__device__ __forceinline__ u32 smem_u32(const void* p) {
    u32 a;
    asm("{ .reg .u64 t; cvta.to.shared.u64 t, %1; cvt.u32.u64 %0, t; }"
        : "=r"(a) : "l"(p));
    return a;
}
__device__ __forceinline__ void cp16(u32 dst, const void* src) {
    asm volatile("cp.async.cg.shared.global [%0], [%1], 16;" :: "r"(dst), "l"(src));
}
#define CP_COMMIT() asm volatile("cp.async.commit_group;" ::: "memory")
#define CP_WAIT0()  asm volatile("cp.async.wait_group 0;" ::: "memory")

__host__ __device__ constexpr int posi(int ci) {
    return ((ci >> 3) << 3) + ((ci & 3) << 1) + ((ci >> 2) & 1);
}
__device__ __forceinline__ int swzf(int f, int s) {
    return ((((f >> 2) ^ s) << 2) | (f & 3));
}

#define A_FLTS (5 * 128 * 16)   // 10240
#define B_ROWS 132
#define B_FLTS (B_ROWS * 16)    // 2112

// ---------------------------------------------------------------------------
// prep kernels (packed [co][pos 16] tiles; swizzle applied at staging time)
// ---------------------------------------------------------------------------
__global__ __launch_bounds__(256)
void prep_w1_kernel(const float* __restrict__ w_n0, const float* __restrict__ w_n1)
{
    int idx = blockIdx.x * 256 + threadIdx.x;
    const int total = 2 * 4 * 5 * 128 * 16;
    if (idx >= total) return;
    int r = idx;
    int ci = r & 15;   r >>= 4;
    int co = r & 127;  r >>= 7;
    int tap = r % 5;   r /= 5;
    int chunk = r & 3; r >>= 2;
    int net = r;
    const float* w = net ? w_n1 : w_n0;
    float v = w[(size_t)co * 320 + (chunk * 16 + ci) * 5 + tap];
    g_w1tf[net][chunk][tap][co][posi(ci)] = __uint_as_float(to_tf32(v));
}

__global__ __launch_bounds__(256)
void prep_w2_kernel(const float* __restrict__ w_n0, const float* __restrict__ w_n1)
{
    int idx = blockIdx.x * 256 + threadIdx.x;
    const int total = 2 * 2 * 8 * 5 * 128 * 16;
    if (idx >= total) return;
    int r = idx;
    int ci = r & 15;   r >>= 4;
    int co = r & 127;  r >>= 7;
    int tap = r % 5;   r /= 5;
    int chunk = r & 7; r >>= 3;
    int coh = r & 1;   r >>= 1;
    int net = r;
    const float* w = net ? w_n1 : w_n0;
    float v = w[(size_t)(coh * 128 + co) * 640 + (chunk * 16 + ci) * 5 + tap];
    g_w2tf[net][coh][chunk][tap][co][posi(ci)] = __uint_as_float(to_tf32(v));
}

// ---------------------------------------------------------------------------
// A stage: cp.async packed [640 rows][16] -> swizzled pitch-16 smem tile
// ---------------------------------------------------------------------------
#define STAGE_A(uAs, srcp)                                                     \
    {                                                                          \
        const char* _src = (const char*)(srcp);                                \
        _Pragma("unroll")                                                      \
        for (int r = 0; r < 10; r++) {                                         \
            int i = r * 256 + tid;                                             \
            int row = i >> 2, seg = i & 3;                                     \
            int off = (row << 4) + (((seg ^ (row & 3)) << 2));                 \
            cp16((uAs) + (u32)off * 4, _src + (size_t)i * 16);                 \
        }                                                                      \
    }

// ---------------------------------------------------------------------------
// MMA over one staged chunk (5 taps), warp tile 32co x 64t (j = 0..7).
// ---------------------------------------------------------------------------
#define MMA_CHUNK(As, BeT, BoT)                                                \
    {                                                                          \
        const int sA = lr & 3;                                                 \
        const int offA0 = swzf(2 * lc, sA);                                    \
        const int offA1 = swzf(2 * lc + 8, sA);                                \
        _Pragma("unroll")                                                      \
        for (int tap = 0; tap < 5; tap++) {                                    \
            const float* Bb = (tap == 1 || tap == 3) ? (BeT) : (BoT);          \
            const int roff = (tap < 2) ? 0 : ((tap == 4) ? 2 : 1);             \
            const int sB = (lr + roff) & 3;                                    \
            const int offB0 = swzf(2 * lc, sB);                                \
            const int offB1 = swzf(2 * lc + 8, sB);                            \
            u32 a[2][2][4];                                                    \
            _Pragma("unroll")                                                  \
            for (int m = 0; m < 2; m++) {                                      \
                const float* ab = (As) + (tap * 128 + wco + m * 16 + lr) * 16; \
                _Pragma("unroll")                                              \
                for (int h = 0; h < 2; h++) {                                  \
                    int oa = h ? offA1 : offA0;                                \
                    float2 q0 = *(const float2*)&ab[oa];                       \
                    float2 q1 = *(const float2*)&ab[128 + oa];                 \
                    a[m][h][0] = __float_as_uint(q0.x);                        \
                    a[m][h][1] = __float_as_uint(q1.x);                        \
                    a[m][h][2] = __float_as_uint(q0.y);                        \
                    a[m][h][3] = __float_as_uint(q1.y);                        \
                }                                                              \
            }                                                                  \
            const float* bb = Bb + (wt + lr + roff) * 16;                      \
            _Pragma("unroll")                                                  \
            for (int h = 0; h < 2; h++) {                                      \
                int ob = h ? offB1 : offB0;                                    \
                _Pragma("unroll")                                              \
                for (int j = 0; j < 8; j++) {                                  \
                    float2 p = *(const float2*)&bb[j * 128 + ob];              \
                    u32 pb0 = __float_as_uint(p.x);                            \
                    u32 pb1 = __float_as_uint(p.y);                            \
                    mma_tf32(acc[0][j], a[0][h], pb0, pb1);                    \
                    mma_tf32(acc[1][j], a[1][h], pb0, pb1);                    \
                }                                                              \
            }                                                                  \
        }                                                                      \
    }

// ---------------------------------------------------------------------------
// conv01: conv0 on the fly (fma2) + conv1 tf32 mma; output -> g_ae/g_ao in
// conv2-ready format (parity split, interleaved cols, tf32 rounded).
// grid (512 b, 8 t-tiles), 256 threads. CTA 128co x 128t.
// smem floats: As[10240] | Be[2112] | Bo[2112] | xs0[1048] | w0d[640] | b0d[64]
// ---------------------------------------------------------------------------
#define O1_BE  A_FLTS
#define O1_BO  (O1_BE + B_FLTS)
#define O1_X   (O1_BO + B_FLTS)
#define O1_W   (O1_X + 1048)
#define O1_BD  (O1_W + 640)
#define C1_SMEM ((O1_BD + 64) * 4)     // 64,864 bytes -> 2 CTAs/SM

__global__ __launch_bounds__(256, 2)
void conv01_mma_kernel(const float* __restrict__ x,
                       const float* __restrict__ w0,  // [64,2,5]
                       const float* __restrict__ b0,  // [64]
                       const float* __restrict__ b1,  // [128]
                       int net)
{
    extern __shared__ float sm[];
    float* As  = sm;
    float* Be  = sm + O1_BE;
    float* Bo  = sm + O1_BO;
    float* xs0 = sm + O1_X;
    ull*   w0d = (ull*)(sm + O1_W);   // [chunk4][grp8][k10] pairs (ci, ci+4)
    ull*   b0d = (ull*)(sm + O1_BD);  // [chunk4][grp8]

    const int tid  = threadIdx.x;
    const int lane = tid & 31;
    const int wid  = tid >> 5;
    const int b    = blockIdx.x;
    const int tt0  = blockIdx.y * 128;

    const int wco = (wid & 3) * 32;
    const int wt  = (wid >> 2) * 64;
    const int lr  = lane >> 2;
    const int lc  = lane & 3;
    const u32 uAs = smem_u32(As);

    // ---- one-time loads: x window, paired w0/b0 ----
    {
        const int x0 = 4 * tt0 - 3;
        const float* xb = x + (size_t)b * 2 * 4096;
#pragma unroll
        for (int row = 0; row < 2; row++)
            for (int col = tid; col < 524; col += 256) {
                int gx = x0 + col;
                xs0[row * 524 + col] =
                    (gx >= 0 && gx < 4096) ? xb[(size_t)row * 4096 + gx] : 0.0f;
            }
        for (int i = tid; i < 320; i += 256) {
            int k = i % 10, g = (i / 10) & 7, ch = i / 80;
            int ci = ch * 16 + (g & 3) + ((g >> 2) << 3);
            w0d[i] = pack2(w0[ci * 10 + k], w0[(ci + 4) * 10 + k]);
        }
        if (tid < 32) {
            int ch = tid >> 3, g = tid & 7;
            int ci = ch * 16 + (g & 3) + ((g >> 2) << 3);
            b0d[tid] = pack2(b0[ci], b0[ci + 4]);
        }
    }

    float acc[2][8][4];
#pragma unroll
    for (int m = 0; m < 2; m++)
#pragma unroll
        for (int j = 0; j < 8; j++)
#pragma unroll
            for (int e = 0; e < 4; e++) acc[m][j][e] = 0.0f;

    __syncthreads();   // xs0/w0d visible

    for (int chunk = 0; chunk < 4; chunk++) {
        // ---- A stage (cp.async) ----
        STAGE_A(uAs, &g_w1tf[net][chunk][0][0][0]);
        CP_COMMIT();

        // ---- B stage: conv0 via fma2 into swizzled parity-split tiles ----
        // rows: Be 0..128 (129), Bo 0..129 (130) -> 259 rows
        {
            const ull* wch = w0d + chunk * 80;
            const ull* bch = b0d + chunk * 8;
            for (int r = tid; r < 259; r += 256) {
                int tau, cb, sB;
                float* dst;
                if (r < 129) {           // even: Be[r] = a0(2*tt0 + 2r)
                    tau = 2 * tt0 + 2 * r;
                    cb  = 4 * r + 2;
                    dst = Be + r * 16;
                    sB  = r & 3;
                } else {                 // odd: Bo[mm] = a0(2*tt0 + 2mm - 1)
                    int mm = r - 129;
                    tau = 2 * tt0 + 2 * mm - 1;
                    cb  = 4 * mm;
                    dst = Bo + mm * 16;
                    sB  = mm & 3;
                }
                if (tau >= 0 && tau < 2048) {
                    ull xp[10];
#pragma unroll
                    for (int k = 0; k < 5; k++) {
                        float v = xs0[cb + k];
                        xp[k] = pack2(v, v);
                    }
#pragma unroll
                    for (int k = 0; k < 5; k++) {
                        float v = xs0[524 + cb + k];
                        xp[5 + k] = pack2(v, v);
                    }
#pragma unroll
                    for (int g = 0; g < 8; g++) {
                        ull a2 = bch[g];
                        const ull* wg = wch + g * 10;
#pragma unroll
                        for (int q = 0; q < 10; q++) fma2(a2, wg[q], xp[q]);
                        float lo, hi;
                        unpack2(a2, lo, hi);
                        float2 vv = make_float2(
                            __uint_as_float(to_tf32(fmaxf(lo, 0.0f))),
                            __uint_as_float(to_tf32(fmaxf(hi, 0.0f))));
                        int off = (((g >> 1) ^ sB) << 2) | ((g & 1) << 1);
                        *(float2*)&dst[off] = vv;
                    }
                } else {
#pragma unroll
                    for (int g = 0; g < 8; g++) {
                        int off = (((g >> 1) ^ sB) << 2) | ((g & 1) << 1);
                        *(float2*)&dst[off] = make_float2(0.0f, 0.0f);
                    }
                }
            }
        }
        CP_WAIT0();
        __syncthreads();

        MMA_CHUNK(As, Be, Bo)
        __syncthreads();
    }

    // ---- epilogue: bias+relu, tf32-round, write ae/ao (interleaved cols).
    //      co = wco+m*16+lr (+8), t = tt0 + wt + j*8 + 2lc (+1).
    //      ae row = t/2, ao row = t/2 + 1. ----
#pragma unroll
    for (int m = 0; m < 2; m++) {
        int co_a = wco + m * 16 + lr;        // co&15 = lr
        int colA = wco + m * 16 + posi(lr);
        int colB = colA + 8;                 // posi(lr+8) = posi(lr)+8
        float bva = b1[co_a];
        float bvb = b1[co_a + 8];
#pragma unroll
        for (int j = 0; j < 8; j++) {
            int rE = (tt0 + wt + j * 8) / 2 + lc;   // ae row for even t
            g_ae[b][rE][colA] = __uint_as_float(
                to_tf32(fmaxf(acc[m][j][0] + bva, 0.0f)));
            g_ao[b][rE + 1][colA] = __uint_as_float(
                to_tf32(fmaxf(acc[m][j][1] + bva, 0.0f)));
            g_ae[b][rE][colB] = __uint_as_float(
                to_tf32(fmaxf(acc[m][j][2] + bvb, 0.0f)));
            g_ao[b][rE + 1][colB] = __uint_as_float(
                to_tf32(fmaxf(acc[m][j][3] + bvb, 0.0f)));
        }
    }
}

// ---------------------------------------------------------------------------
// conv2: tf32 warp-MMA + fused pool. B staging = pure cp.async from the
// pre-formatted g_ae/g_ao (64B rows -> swizzled smem, zero compute).
// grid (512 b, 4 t-tiles, 2 co-halves), 256 threads. CTA 128co x 128t.
// smem floats: As[10240] | Be[2112] | Bo[2112]
// ---------------------------------------------------------------------------
#define O2_BE  A_FLTS
#define O2_BO  (O2_BE + B_FLTS)
#define C2_SMEM ((O2_BO + B_FLTS) * 4)   // 57,856 bytes -> 2 CTAs/SM

__global__ __launch_bounds__(256, 2)
void conv2_mma_kernel(const float* __restrict__ bias,  // [256]
                      float* __restrict__ feat,        // [512,256] sums
                      int net)
{
    extern __shared__ float sm[];
    float* As = sm;
    float* Be = sm + O2_BE;
    float* Bo = sm + O2_BO;

    const int tid  = threadIdx.x;
    const int lane = tid & 31;
    const int wid  = tid >> 5;
    const int b    = blockIdx.x;
    const int tt0  = blockIdx.y * 128;
    const int co0  = blockIdx.z * 128;

    const int wco = (wid & 3) * 32;
    const int wt  = (wid >> 2) * 64;
    const int lr  = lane >> 2;
    const int lc  = lane & 3;
    const u32 uAs = smem_u32(As);
    const u32 uBe = smem_u32(Be);
    const u32 uBo = smem_u32(Bo);

    float acc[2][8][4];
#pragma unroll
    for (int m = 0; m < 2; m++)
#pragma unroll
        for (int j = 0; j < 8; j++)
#pragma unroll
            for (int e = 0; e < 4; e++) acc[m][j][e] = 0.0f;

    for (int chunk = 0; chunk < 8; chunk++) {
        const int ci0 = chunk * 16;
        // ---- A stage (cp.async) ----
        STAGE_A(uAs, &g_w2tf[net][co0 >> 7][chunk][0][0][0]);
        // ---- B stage (cp.async from pre-formatted ae/ao):
        //      Be rows 0..128 (129*4 segs = 516), Bo rows 0..129 (520) ----
        for (int i = tid; i < 1036; i += 256) {
            int rr = i >> 2, seg = i & 3;
            if (rr < 129) {
                const char* src =
                    (const char*)&g_ae[b][tt0 + rr][ci0] + seg * 16;
                cp16(uBe + (u32)(rr * 16 + ((seg ^ (rr & 3)) << 2)) * 4, src);
            } else {
                int m = rr - 129;
                const char* src =
                    (const char*)&g_ao[b][tt0 + m][ci0] + seg * 16;
                cp16(uBo + (u32)(m * 16 + ((seg ^ (m & 3)) << 2)) * 4, src);
            }
        }
        CP_COMMIT();
        CP_WAIT0();
        __syncthreads();

        MMA_CHUNK(As, Be, Bo)
        __syncthreads();
    }

    // ---- epilogue: bias+relu, sum over t, quad-reduce, atomicAdd ----
    float* fb = feat + (size_t)b * 256;
#pragma unroll
    for (int m = 0; m < 2; m++) {
        int r0 = co0 + wco + m * 16 + lr;
        int r1 = r0 + 8;
        float bv0 = __ldg(&bias[r0]);
        float bv1 = __ldg(&bias[r1]);
        float s0 = 0.0f, s1 = 0.0f;
#pragma unroll
        for (int j = 0; j < 8; j++) {
            s0 += fmaxf(acc[m][j][0] + bv0, 0.0f) + fmaxf(acc[m][j][1] + bv0, 0.0f);
            s1 += fmaxf(acc[m][j][2] + bv1, 0.0f) + fmaxf(acc[m][j][3] + bv1, 0.0f);
        }
        s0 += __shfl_xor_sync(0xffffffffu, s0, 1);
        s0 += __shfl_xor_sync(0xffffffffu, s0, 2);
        s1 += __shfl_xor_sync(0xffffffffu, s1, 1);
        s1 += __shfl_xor_sync(0xffffffffu, s1, 2);
        if (lc == 0) {
            atomicAdd(&fb[r0], s0);
            atomicAdd(&fb[r1], s1);
        }
    }
}

// ---------------------------------------------------------------------------
__global__ void zero_feat_kernel()
{
    int i = blockIdx.x * 256 + threadIdx.x;
    if (i < 2 * 512 * 256) ((float*)g_feat)[i] = 0.0f;
}

// ---------------------------------------------------------------------------
// heads + softmax + hierarchical routing. 1 warp per sample.
// ---------------------------------------------------------------------------
__global__ __launch_bounds__(32)
void head_kernel(const float* __restrict__ wh1, const float* __restrict__ bh1,
                 const float* __restrict__ wh2, const float* __restrict__ bh2,
                 float* __restrict__ out)
{
    const int b = blockIdx.x;
    const int lane = threadIdx.x;
    const float* f1 = &g_feat[0][b][0];
    const float* f2 = &g_feat[1][b][0];
    const float inv_pool = 1.0f / 512.0f;

    float lg1[3], lg2[2];
#pragma unroll
    for (int cls = 0; cls < 3; cls++) {
        float s = 0.0f;
        for (int c = lane; c < 256; c += 32) s += f1[c] * wh1[cls * 256 + c];
#pragma unroll
        for (int off = 16; off > 0; off >>= 1) s += __shfl_xor_sync(0xffffffffu, s, off);
        lg1[cls] = s * inv_pool + bh1[cls];
    }
#pragma unroll
    for (int cls = 0; cls < 2; cls++) {
        float s = 0.0f;
        for (int c = lane; c < 256; c += 32) s += f2[c] * wh2[cls * 256 + c];
#pragma unroll
        for (int off = 16; off > 0; off >>= 1) s += __shfl_xor_sync(0xffffffffu, s, off);
        lg2[cls] = s * inv_pool + bh2[cls];
    }

    if (lane == 0) {
        float m = fmaxf(lg1[0], fmaxf(lg1[1], lg1[2]));
        float e0 = expf(lg1[0] - m), e1 = expf(lg1[1] - m), e2 = expf(lg1[2] - m);
        float inv = 1.0f / (e0 + e1 + e2);
        float p0 = e0 * inv, p1 = e1 * inv, p2 = e2 * inv;
        int pred = 0; float best = p0;
        if (p1 > best) { best = p1; pred = 1; }
        if (p2 > best) { best = p2; pred = 2; }

        float m2 = fmaxf(lg2[0], lg2[1]);
        float q0 = expf(lg2[0] - m2), q1 = expf(lg2[1] - m2);
        float inv2 = 1.0f / (q0 + q1);
        q0 *= inv2; q1 *= inv2;

        out[b * 4 + 0] = (pred == 0) ? p0 : 0.0f;
        out[b * 4 + 1] = (pred == 1) ? p1 : 0.0f;
        out[b * 4 + 2] = (pred == 2) ? q0 : 0.0f;
        out[b * 4 + 3] = (pred == 2) ? q1 : 0.0f;
    }
}

// ---------------------------------------------------------------------------
extern "C" void kernel_launch(void* const* d_in, const int* in_sizes, int n_in,
                              void* d_out, int out_size)
{
    (void)in_sizes; (void)n_in; (void)out_size;
    const float* x = (const float*)d_in[0];

    const float* W[2][8];
    for (int net = 0; net < 2; net++)
        for (int i = 0; i < 8; i++)
            W[net][i] = (const float*)d_in[1 + net * 8 + i];

    float* out = (float*)d_out;

    float* feat;
    cudaGetSymbolAddress((void**)&feat, g_feat);

    cudaFuncSetAttribute(conv01_mma_kernel,
                         cudaFuncAttributeMaxDynamicSharedMemorySize, C1_SMEM);
    cudaFuncSetAttribute(conv2_mma_kernel,
                         cudaFuncAttributeMaxDynamicSharedMemorySize, C2_SMEM);

    zero_feat_kernel<<<1024, 256>>>();
    prep_w1_kernel<<<320, 256>>>(W[0][2], W[1][2]);
    prep_w2_kernel<<<1280, 256>>>(W[0][4], W[1][4]);

    for (int net = 0; net < 2; net++) {
        conv01_mma_kernel<<<dim3(512, 8), 256, C1_SMEM>>>(
            x, W[net][0], W[net][1], W[net][3], net);
        conv2_mma_kernel<<<dim3(512, 4, 2), 256, C2_SMEM>>>(
            W[net][5], feat + (size_t)net * 512 * 256, net);
    }

    head_kernel<<<512, 32>>>(W[0][6], W[0][7], W[1][6], W[1][7], out);
}